// round 13
// baseline (speedup 1.0000x reference)
#include <cuda_runtime.h>
#include <cstdint>

#define BATCH 8
#define SEQ   2048
#define EMBD  1024

#define TILE    128
#define STAGES  3
#define A_BYTES      16384              // 128 rows x 128B (swizzled)
#define STAGE_STD    32768              // A + B (both swizzled)
#define B_PV_STRIDE  136                // floats per V row in smem (128 + 8 pad)
#define B_PV_BYTES   (32*B_PV_STRIDE*4) // 17408
#define STAGE_PV     (A_BYTES + B_PV_BYTES)

// ---- scratch (__device__ globals; allocation is forbidden) ----
__device__ float g_Q [(size_t)BATCH*SEQ*EMBD];
__device__ float g_K [(size_t)BATCH*SEQ*EMBD];
__device__ float g_V [(size_t)BATCH*SEQ*EMBD];
__device__ float g_Wr[3*(size_t)EMBD*EMBD];     // tf32-rounded Wq|Wk|Wv
__device__ float g_rowsum[BATCH*SEQ];

__device__ __forceinline__ float f2tf32(float x){
  uint32_t u; asm("cvt.rna.tf32.f32 %0, %1;" : "=r"(u) : "f"(x));
  return __uint_as_float(u);
}
__device__ __forceinline__ uint32_t cvt_u(uint32_t x){
  uint32_t u; asm("cvt.rna.tf32.f32 %0, %1;" : "=r"(u) : "r"(x));
  return u;
}
__device__ __forceinline__ void cp16s(uint32_t sm, const void* gm){
  asm volatile("cp.async.cg.shared.global [%0], [%1], 16;" :: "r"(sm), "l"(gm));
}
__device__ __forceinline__ void ldsm4(uint32_t& r0,uint32_t& r1,uint32_t& r2,uint32_t& r3,
                                      uint32_t s){
  asm volatile("ldmatrix.sync.aligned.m8n8.x4.shared.b16 {%0,%1,%2,%3}, [%4];"
    : "=r"(r0),"=r"(r1),"=r"(r2),"=r"(r3) : "r"(s));
}

// 3 weight matrices rounded in one launch (z = matrix id)
__global__ void round_copy3(const float* __restrict__ a, const float* __restrict__ b,
                            const float* __restrict__ c, float* __restrict__ dst){
  const float* s = blockIdx.z==0 ? a : (blockIdx.z==1 ? b : c);
  float* d = dst + (size_t)blockIdx.z*EMBD*EMBD;
  const long i = (long)blockIdx.x*blockDim.x + threadIdx.x;
  float4 v = reinterpret_cast<const float4*>(s)[i];
  v.x = f2tf32(v.x); v.y = f2tf32(v.y); v.z = f2tf32(v.z); v.w = f2tf32(v.w);
  reinterpret_cast<float4*>(d)[i] = v;
}

// ============================================================================
// tf32 GEMM:  C[m][n] = sum_k A[m][k] * B[n][k]
// MODE 0: fused QKV proj. A = raw x|ctx (cvt after LDSM), B = rounded weights.
// MODE 1: scores. A=Q B=K (pre-rounded). epi: mask/exp/rowsum, writes raw exp.
// MODE 2: out.    A=att raw exp, B = V row-major [k][n] via scalar LDS ("nn").
// CTA 128x128x32, 256 thr, 8 warps (2x4), warp 64x32, 3-stage cp.async.
// ============================================================================
template<int MODE>
__global__ __launch_bounds__(256, 2)
void gemm_tf32(const float* __restrict__ Ag, const float* __restrict__ Aalt,
               const float* __restrict__ Bg,
               float* __restrict__ Cg, float* __restrict__ Cq1, float* __restrict__ Cq2,
               const float* __restrict__ bias, const float* __restrict__ bias1,
               const float* __restrict__ bias2,
               const int*   __restrict__ maskg, float* __restrict__ rowsum,
               int N, int Kd,
               long bA, long bB, long bC, long bM, int bRS,
               float scale)
{
  constexpr int STAGE_BYTES = (MODE == 2) ? STAGE_PV : STAGE_STD;
  extern __shared__ float smem[];
  uint32_t smbase = (uint32_t)__cvta_generic_to_shared(smem);

  const int b  = blockIdx.z;
  const int m0 = blockIdx.y * TILE;
  const int n0 = blockIdx.x * TILE;

  const float* A;
  const float* B;
  float*       C;
  const float* bs = bias;
  int n0l = n0;
  if constexpr (MODE == 0){
    const int mat = n0 >> 10;                // 0:Q 1:K 2:V
    n0l = n0 & 1023;
    A  = (mat == 0) ? Ag : Aalt;
    C  = (mat == 0) ? Cg : (mat == 1 ? Cq1 : Cq2);
    bs = (mat == 0) ? bias : (mat == 1 ? bias1 : bias2);
    B  = Bg;                                 // weight rows n0..n0+127 of 3072
  } else {
    A = Ag + (long)b*bA;
    B = Bg + (long)b*bB;
    C = Cg + (long)b*bC;
  }

  const int tid  = threadIdx.x;
  const int lane = tid & 31;
  const int warp = tid >> 5;
  const int wm = warp >> 2;   // 0..1
  const int wn = warp & 3;    // 0..3
  const int g  = lane >> 2;   // 0..7
  const int t  = lane & 3;    // 0..3

  // ldmatrix per-lane coordinates
  const int aR  = lane & 15;
  const int aC4 = (lane >> 4) & 1;
  const int bR  = (lane & 7) + ((lane & 16) >> 1);
  const int bC4 = (lane >> 3) & 1;

  float c[4][4][4];
  #pragma unroll
  for (int i=0;i<4;i++)
    #pragma unroll
    for (int j=0;j<4;j++){ c[i][j][0]=0.f;c[i][j][1]=0.f;c[i][j][2]=0.f;c[i][j][3]=0.f; }

  const int NT = Kd >> 5;

  auto fill = [&](int kt, int st){
    const int k0 = kt << 5;
    const uint32_t sa = smbase + st*STAGE_BYTES;
    // A tile: 1024 16B chunks, swizzled
    #pragma unroll
    for (int i=0;i<4;i++){
      const int idx = tid + (i<<8);
      const int row = idx >> 3;
      const int ch  = idx & 7;
      const uint32_t off = (uint32_t)(row<<7) + (uint32_t)((ch ^ (row & 7)) << 4);
      cp16s(sa + off, A + (long)(m0+row)*Kd + k0 + (ch<<2));
    }
    if constexpr (MODE == 2){
      // B tile: V[k0..k0+31][n0..n0+127] = 32 rows x 32 chunks = 1024 chunks
      const uint32_t sb = sa + A_BYTES;
      #pragma unroll
      for (int i=0;i<4;i++){
        const int idx = tid + (i<<8);
        const int row = idx >> 5;        // 0..31 (k)
        const int ch  = idx & 31;        // 0..31 (16B chunk within row)
        cp16s(sb + (uint32_t)(row*(B_PV_STRIDE*4)) + (uint32_t)(ch<<4),
              B + (long)(k0+row)*N + n0 + (ch<<2));
      }
    } else {
      const uint32_t sb = sa + A_BYTES;
      #pragma unroll
      for (int i=0;i<4;i++){
        const int idx = tid + (i<<8);
        const int row = idx >> 3;
        const int ch  = idx & 7;
        const uint32_t off = (uint32_t)(row<<7) + (uint32_t)((ch ^ (row & 7)) << 4);
        cp16s(sb + off, B + (long)(n0+row)*Kd + k0 + (ch<<2));
      }
    }
    asm volatile("cp.async.commit_group;");
  };

  uint32_t af[4][4], bf[4][2];

  auto load_frags = [&](int st, int kk){
    const uint32_t sa = smbase + st*STAGE_BYTES;
    const int kc = kk >> 2;
    #pragma unroll
    for (int mt=0; mt<4; mt++){
      const int R = wm*64 + mt*16 + aR;
      ldsm4(af[mt][0], af[mt][1], af[mt][2], af[mt][3],
            sa + (uint32_t)(R<<7) + (uint32_t)((((kc + aC4) ^ (R & 7))) << 4));
    }
    if constexpr (MODE == 0){
      #pragma unroll
      for (int mt=0; mt<4; mt++){
        af[mt][0] = cvt_u(af[mt][0]); af[mt][1] = cvt_u(af[mt][1]);
        af[mt][2] = cvt_u(af[mt][2]); af[mt][3] = cvt_u(af[mt][3]);
      }
    }
    if constexpr (MODE == 2){
      // scalar LDS from [k][n] layout: bf[nt][r] = B[kk + t + 4r][wn*32 + nt*8 + g]
      const float* sBf = smem + (st*STAGE_BYTES + A_BYTES)/4;
      const float* p = sBf + (kk + t)*B_PV_STRIDE + wn*32 + g;
      #pragma unroll
      for (int nt=0; nt<4; nt++){
        bf[nt][0] = __float_as_uint(p[nt*8]);
        bf[nt][1] = __float_as_uint(p[4*B_PV_STRIDE + nt*8]);
      }
    } else {
      const uint32_t sb = smbase + st*STAGE_BYTES + A_BYTES;
      #pragma unroll
      for (int np=0; np<2; np++){
        const int R = wn*32 + np*16 + bR;
        ldsm4(bf[2*np][0], bf[2*np][1], bf[2*np+1][0], bf[2*np+1][1],
              sb + (uint32_t)(R<<7) + (uint32_t)((((kc + bC4) ^ (R & 7))) << 4));
      }
    }
  };

  auto mmas = [&](){
    #pragma unroll
    for (int mt=0; mt<4; mt++)
      #pragma unroll
      for (int nt=0; nt<4; nt++){
        asm volatile(
          "mma.sync.aligned.m16n8k8.row.col.f32.tf32.tf32.f32 "
          "{%0,%1,%2,%3}, {%4,%5,%6,%7}, {%8,%9}, {%0,%1,%2,%3};"
          : "+f"(c[mt][nt][0]), "+f"(c[mt][nt][1]),
            "+f"(c[mt][nt][2]), "+f"(c[mt][nt][3])
          : "r"(af[mt][0]), "r"(af[mt][1]), "r"(af[mt][2]), "r"(af[mt][3]),
            "r"(bf[nt][0]), "r"(bf[nt][1]));
      }
  };

  fill(0, 0);
  if (NT > 1) fill(1, 1);

  for (int kt=0; kt<NT; kt++){
    const int cur = kt % STAGES;
    if (kt + STAGES - 1 < NT) fill(kt + STAGES - 1, (kt + STAGES - 1) % STAGES);
    else                      asm volatile("cp.async.commit_group;");
    asm volatile("cp.async.wait_group %0;" :: "n"(STAGES-1));
    __syncthreads();

    #pragma unroll
    for (int kk8=0; kk8<4; kk8++){
      load_frags(cur, kk8*8);
      mmas();
    }
    __syncthreads();
  }

  // ---------------- epilogues ----------------
  if constexpr (MODE == 0){
    #pragma unroll
    for (int mt=0; mt<4; mt++){
      const int r0 = m0 + wm*64 + mt*16 + g;
      #pragma unroll
      for (int nt=0; nt<4; nt++){
        const int cc = n0l + wn*32 + nt*8 + 2*t;
        const float b0 = bs[cc], b1 = bs[cc+1];
        *reinterpret_cast<float2*>(&C[(long)r0*EMBD + cc]) =
            make_float2(f2tf32(c[mt][nt][0]+b0), f2tf32(c[mt][nt][1]+b1));
        *reinterpret_cast<float2*>(&C[(long)(r0+8)*EMBD + cc]) =
            make_float2(f2tf32(c[mt][nt][2]+b0), f2tf32(c[mt][nt][3]+b1));
      }
    }
  } else if constexpr (MODE == 1){
    const int* Mk = maskg + (long)b*bM;
    #pragma unroll
    for (int mt=0; mt<4; mt++){
      float rs0 = 0.f, rs1 = 0.f;
      const int r0 = m0 + wm*64 + mt*16 + g;
      #pragma unroll
      for (int nt=0; nt<4; nt++){
        const int cc = n0 + wn*32 + nt*8 + 2*t;
        const long i0 = (long)r0*N + cc;
        const long i1 = (long)(r0+8)*N + cc;
        int2 m0v = *reinterpret_cast<const int2*>(&Mk[i0]);
        int2 m1v = *reinterpret_cast<const int2*>(&Mk[i1]);
        float e0 = m0v.x ? 0.f : f2tf32(__expf(c[mt][nt][0]*scale));
        float e1 = m0v.y ? 0.f : f2tf32(__expf(c[mt][nt][1]*scale));
        float e2 = m1v.x ? 0.f : f2tf32(__expf(c[mt][nt][2]*scale));
        float e3 = m1v.y ? 0.f : f2tf32(__expf(c[mt][nt][3]*scale));
        *reinterpret_cast<float2*>(&C[i0]) = make_float2(e0, e1);
        *reinterpret_cast<float2*>(&C[i1]) = make_float2(e2, e3);
        rs0 += e0 + e1;
        rs1 += e2 + e3;
      }
      rs0 += __shfl_xor_sync(0xffffffffu, rs0, 1);
      rs0 += __shfl_xor_sync(0xffffffffu, rs0, 2);
      rs1 += __shfl_xor_sync(0xffffffffu, rs1, 1);
      rs1 += __shfl_xor_sync(0xffffffffu, rs1, 2);
      if (t == 0){
        atomicAdd(&rowsum[b*bRS + r0    ], rs0);
        atomicAdd(&rowsum[b*bRS + r0 + 8], rs1);
      }
    }
  } else { // MODE 2
    #pragma unroll
    for (int mt=0; mt<4; mt++){
      const int r0 = m0 + wm*64 + mt*16 + g;
      const float inv0 = 1.0f / rowsum[b*bRS + r0    ];
      const float inv1 = 1.0f / rowsum[b*bRS + r0 + 8];
      #pragma unroll
      for (int nt=0; nt<4; nt++){
        const int cc = n0 + wn*32 + nt*8 + 2*t;
        *reinterpret_cast<float2*>(&C[(long)r0*N + cc])     = make_float2(c[mt][nt][0]*inv0, c[mt][nt][1]*inv0);
        *reinterpret_cast<float2*>(&C[(long)(r0+8)*N + cc]) = make_float2(c[mt][nt][2]*inv1, c[mt][nt][3]*inv1);
      }
    }
  }
}

__global__ void init_zero(float* p){
  p[blockIdx.x*1024 + threadIdx.x] = 0.f;
}

__global__ void norm_att(float* __restrict__ att, const float* __restrict__ rowsum){
  const long gid = (long)blockIdx.x*blockDim.x + threadIdx.x;
  const long row = gid >> 9;
  const float inv = 1.0f / rowsum[row];
  float4 v = reinterpret_cast<float4*>(att)[gid];
  v.x *= inv; v.y *= inv; v.z *= inv; v.w *= inv;
  reinterpret_cast<float4*>(att)[gid] = v;
}

extern "C" void kernel_launch(void* const* d_in, const int* in_sizes, int n_in,
                              void* d_out, int out_size)
{
  const float* x   = (const float*)d_in[0];
  const float* ctx = (const float*)d_in[1];
  const int*   msk = (const int*)  d_in[2];
  const float* Wq  = (const float*)d_in[3];
  const float* bq  = (const float*)d_in[4];
  const float* Wk  = (const float*)d_in[5];
  const float* bk  = (const float*)d_in[6];
  const float* Wv  = (const float*)d_in[7];
  const float* bv  = (const float*)d_in[8];

  float* out = (float*)d_out;                   // [8][2048][1024]
  float* att = out + (size_t)BATCH*SEQ*EMBD;    // [8][2048][2048]

  float *qp, *kp, *vp, *rsp, *wr;
  cudaGetSymbolAddress((void**)&qp,  g_Q);
  cudaGetSymbolAddress((void**)&kp,  g_K);
  cudaGetSymbolAddress((void**)&vp,  g_V);
  cudaGetSymbolAddress((void**)&rsp, g_rowsum);
  cudaGetSymbolAddress((void**)&wr,  g_Wr);

  const int SMEM_STD_T = STAGES*STAGE_STD;   // 98304
  const int SMEM_PV_T  = STAGES*STAGE_PV;    // 101376
  cudaFuncSetAttribute(gemm_tf32<0>, cudaFuncAttributeMaxDynamicSharedMemorySize, SMEM_STD_T);
  cudaFuncSetAttribute(gemm_tf32<1>, cudaFuncAttributeMaxDynamicSharedMemorySize, SMEM_STD_T);
  cudaFuncSetAttribute(gemm_tf32<2>, cudaFuncAttributeMaxDynamicSharedMemorySize, SMEM_PV_T);

  const dim3 blk(256);

  round_copy3<<<dim3(EMBD*EMBD/4/256, 1, 3), 256>>>(Wq, Wk, Wv, wr);
  init_zero<<<16, 1024>>>(rsp);

  // fused QKV projection (M=16384, N=3072 concat, K=1024); A raw, cvt in-loop
  gemm_tf32<0><<<dim3(3*EMBD/TILE, (BATCH*SEQ)/TILE, 1), blk, SMEM_STD_T>>>(
      x, ctx, wr, qp, kp, vp, bq, bk, bv, nullptr, nullptr,
      EMBD, EMBD, 0,0,0,0,0, 1.f);

  // scores (M=SEQ, N=SEQ, K=EMBD)
  gemm_tf32<1><<<dim3(SEQ/TILE, SEQ/TILE, BATCH), blk, SMEM_STD_T>>>(
      qp, nullptr, kp, att, nullptr, nullptr, nullptr, nullptr, nullptr,
      msk, rsp, SEQ, EMBD,
      (long)SEQ*EMBD, (long)SEQ*EMBD, (long)SEQ*SEQ, (long)SEQ*SEQ, SEQ, 0.03125f);

  // out = (raw_exp . V)/rowsum   (M=SEQ, N=EMBD, K=SEQ; B = V row-major)
  gemm_tf32<2><<<dim3(EMBD/TILE, SEQ/TILE, BATCH), blk, SMEM_PV_T>>>(
      att, nullptr, vp, out, nullptr, nullptr, nullptr, nullptr, nullptr,
      nullptr, rsp, EMBD, SEQ,
      (long)SEQ*SEQ, (long)SEQ*EMBD, (long)SEQ*EMBD, 0, SEQ, 1.f);

  // finalize att in place
  norm_att<<<(int)(((long)BATCH*SEQ*SEQ/4)/256), 256>>>(att, rsp);
}